// round 10
// baseline (speedup 1.0000x reference)
#include <cuda_runtime.h>
#include <math.h>
#include <stdint.h>

#define NG 1000

// x as pre-swizzled bf16 hi/lo slot image: 4 slots x (hi 8K | lo 8K)
__device__ __align__(16) char g_ximg[65536];
// h1 as pre-swizzled slot image per gene: 16 slots x 16KB
__device__ __align__(16) char g_h1img[(size_t)NG * 262144];
__device__ float g_part[(size_t)NG * 4 * 128];

// k1 smem: b1s@0(1K) | A static@1024(64K) | B ring@66560 (3 x 16K)
#define K1_A 1024
#define K1_B 66560
#define SM1_BYTES 115712
// k2 smem: b2s@0 w3s@512 red@1024(2K) | ring@4096: 3 slots x 32K (Ah8K Al8K Bh8K Bl8K)
#define K2_R 4096
#define SM2_BYTES 102400

// named barrier ids
#define BFULL 1   // 1,2,3
#define BEMPTY 4  // 4,5,6
#define BCONS 7

__device__ __forceinline__ uint32_t smem_u32(const void* p){
    uint32_t a;
    asm("{ .reg .u64 t; cvta.to.shared.u64 t, %1; cvt.u32.u64 %0, t; }" : "=r"(a) : "l"(p));
    return a;
}
__device__ __forceinline__ uint32_t sw64(uint32_t x){ return x ^ ((x >> 3) & 0x30u); }

__device__ __forceinline__ void split2(float f0, float f1, uint32_t& hp, uint32_t& lp){
    asm("cvt.rn.bf16x2.f32 %0, %1, %2;" : "=r"(hp) : "f"(f1), "f"(f0));
    float h1f = __uint_as_float(hp & 0xFFFF0000u);
    float h0f = __uint_as_float(hp << 16);
    asm("cvt.rn.bf16x2.f32 %0, %1, %2;" : "=r"(lp) : "f"(f1 - h1f), "f"(f0 - h0f));
}
__device__ __forceinline__ float gelu(float v){
    return 0.5f * v * (1.0f + erff(v * 0.70710678118654752440f));
}
__device__ __forceinline__ void ldsm4(uint32_t* r, uint32_t a){
    asm volatile("ldmatrix.sync.aligned.m8n8.x4.shared.b16 {%0,%1,%2,%3}, [%4];"
      : "=r"(r[0]), "=r"(r[1]), "=r"(r[2]), "=r"(r[3]) : "r"(a));
}
__device__ __forceinline__ void mmabf(float* c, const uint32_t* a, uint32_t b0, uint32_t b1){
    asm volatile("mma.sync.aligned.m16n8k16.row.col.f32.bf16.bf16.f32 "
      "{%0,%1,%2,%3},{%4,%5,%6,%7},{%8,%9},{%0,%1,%2,%3};"
      : "+f"(c[0]), "+f"(c[1]), "+f"(c[2]), "+f"(c[3])
      : "r"(a[0]), "r"(a[1]), "r"(a[2]), "r"(a[3]), "r"(b0), "r"(b1));
}
#define CP16(d,s)  asm volatile("cp.async.cg.shared.global [%0], [%1], 16;" :: "r"(d), "l"(s) : "memory")
#define CPCOMMIT() asm volatile("cp.async.commit_group;" ::: "memory")
#define CPWAIT0()  asm volatile("cp.async.wait_group 0;" ::: "memory")
#define CPWAIT1()  asm volatile("cp.async.wait_group 1;" ::: "memory")
#define BSYNC(id)  asm volatile("bar.sync %0, 384;"   :: "r"(id) : "memory")
#define BARR(id)   asm volatile("bar.arrive %0, 384;" :: "r"(id) : "memory")
#define BSYNCC()   asm volatile("bar.sync %0, 256;"   :: "r"(BCONS) : "memory")

struct Frag { uint32_t offA, mA, offB, mB, ksel; };

__device__ __forceinline__ Frag mk_frag(int lane, int wm, int wn){
    Frag f;
    uint32_t rA = wm * 64 + (lane & 7) + ((lane >> 3) & 1) * 8;
    uint32_t rB = wn * 32 + (lane & 7) + ((lane >> 3) & 1) * 8;
    f.ksel = ((lane >> 4) & 1) * 16;
    f.mA = ((rA >> 1) & 3) << 4;  f.mB = ((rB >> 1) & 3) << 4;
    f.offA = rA * 64;             f.offB = rB * 64;
    return f;
}

// one K=32 tile, 64B rows. A: aB hi, aB+8192 lo; B: bB hi, bB+8192 lo.
__device__ __forceinline__ void mma32(uint32_t aB, uint32_t bB, const Frag& f, float c[4][4][4])
{
#pragma unroll
    for (int ks = 0; ks < 2; ks++){
        uint32_t ka = ks * 32 + f.ksel;
        uint32_t ao = f.offA + (ka ^ f.mA);
        uint32_t bo = f.offB + (ka ^ f.mB);
        uint32_t ah[4][4], al[4][4], bh[2][4], bl[2][4];
#pragma unroll
        for (int i = 0; i < 4; i++){ ldsm4(ah[i], aB + ao + i*1024u); ldsm4(al[i], aB + 8192u + ao + i*1024u); }
#pragma unroll
        for (int j = 0; j < 2; j++){ ldsm4(bh[j], bB + bo + j*1024u); ldsm4(bl[j], bB + 8192u + bo + j*1024u); }
#pragma unroll
        for (int i = 0; i < 4; i++)
#pragma unroll
        for (int jt = 0; jt < 4; jt++){
            int j = jt >> 1, s2 = jt & 1;
            mmabf(c[i][jt], ah[i], bh[j][s2], bh[j][s2+2]);
            mmabf(c[i][jt], ah[i], bl[j][s2], bl[j][s2+2]);
            mmabf(c[i][jt], al[i], bh[j][s2], bh[j][s2+2]);
        }
    }
}

// producer: convert 32 W floats (rows k=0..31 of column n) -> B planes (row n)
__device__ __forceinline__ void convSts(char* bB, int n, const float* w){
    char* Bh = bB; char* Bl = bB + 8192;
#pragma unroll
    for (int l = 0; l < 32; l += 4){
        uint32_t hp0, lp0, hp1, lp1;
        split2(w[l],   w[l+1], hp0, lp0);
        split2(w[l+2], w[l+3], hp1, lp1);
        uint32_t off = sw64((uint32_t)n * 64 + l * 2);
        *(uint2*)(Bh + off) = make_uint2(hp0, hp1);
        *(uint2*)(Bl + off) = make_uint2(lp0, lp1);
    }
}

// ============ k0: x -> pre-swizzled bf16 hi/lo image (once) ============
__global__ void k0(const float* __restrict__ x)
{
    int tid = threadIdx.x;           // 256
    int m = tid >> 1, h = tid & 1;
    const float4* xr = (const float4*)(x + m * 128 + h * 64);
#pragma unroll
    for (int j4 = 0; j4 < 16; j4++){
        float4 v = xr[j4];
        int l = j4 * 4;
        int slot = h * 2 + (l >> 5);
        int kk = l & 31;
        uint32_t hp0, lp0, hp1, lp1;
        split2(v.x, v.y, hp0, lp0);
        split2(v.z, v.w, hp1, lp1);
        uint32_t off = sw64((uint32_t)m * 64 + kk * 2);
        *(uint2*)(g_ximg + slot * 16384 + off) = make_uint2(hp0, hp1);
        *(uint2*)(g_ximg + slot * 16384 + 8192 + off) = make_uint2(lp0, lp1);
    }
}

// ============ k1: h1 = gelu(x @ W1 + b1) -> h1 slot image ============
// grid (4, 1000). 384 threads: warps 0-7 consumers, 8-11 producers.
__global__ void __launch_bounds__(384, 1)
k1(const float* __restrict__ W1, const float* __restrict__ b1)
{
    extern __shared__ char sm[];
    uint32_t sb = smem_u32(sm);
    const int nc = blockIdx.x, g = blockIdx.y;
    const int tid = threadIdx.x;

    if (tid >= 256){
        // ---------------- producer ----------------
        const int p = tid - 256;                 // 0..127 ; n = p
        const float* Wg = W1 + (size_t)g * 65536 + nc * 128 + p;
        // A image (64KB) via cp.async
#pragma unroll
        for (int i = 0; i < 32; i++){
            uint32_t idx = p + i * 128;
            CP16(sb + K1_A + idx * 16, g_ximg + idx * 16);
        }
        CPCOMMIT();
        float w0[32], w1[32];
#pragma unroll
        for (int l = 0; l < 32; l++) w0[l] = Wg[(size_t)l * 512];
#pragma unroll
        for (int l = 0; l < 32; l++) w1[l] = Wg[(size_t)(32 + l) * 512];

#pragma unroll
        for (int kt = 0; kt < 4; kt++){
            if (kt == 3) BSYNC(BEMPTY + 0);
            convSts(sm + K1_B + (kt % 3) * 16384, p, (kt & 1) ? w1 : w0);
            if (kt == 0){
#pragma unroll
                for (int l = 0; l < 32; l++) w0[l] = Wg[(size_t)(64 + l) * 512];
            } else if (kt == 1){
#pragma unroll
                for (int l = 0; l < 32; l++) w1[l] = Wg[(size_t)(96 + l) * 512];
            }
            if (kt == 0) CPWAIT0();
            BARR(BFULL + kt % 3);
        }
        return;
    }

    // ---------------- consumer ----------------
    const int lane = tid & 31, w = tid >> 5;
    const int wm = w & 1, wn = w >> 1;
    float* b1s = (float*)sm;
    if (tid < 128) b1s[tid] = b1[(size_t)g * 512 + nc * 128 + tid];

    float c[4][4][4];
#pragma unroll
    for (int i = 0; i < 4; i++)
#pragma unroll
    for (int jt = 0; jt < 4; jt++)
#pragma unroll
    for (int q = 0; q < 4; q++) c[i][jt][q] = 0.0f;
    Frag f = mk_frag(lane, wm, wn);

#pragma unroll
    for (int kt = 0; kt < 4; kt++){
        BSYNC(BFULL + kt % 3);
        mma32(sb + K1_A + kt * 16384, sb + K1_B + (kt % 3) * 16384, f, c);
        if (kt == 0) BARR(BEMPTY + 0);
    }

    // epilogue: bias + gelu + split -> h1 slot image
    size_t gbase = (size_t)g * 262144;
#pragma unroll
    for (int i = 0; i < 4; i++)
#pragma unroll
    for (int jt = 0; jt < 4; jt++){
        int nl = wn * 32 + jt * 8 + 2 * (lane & 3);
        int r0 = wm * 64 + i * 16 + (lane >> 2);
        int C = nc * 128 + nl;
        int slot = C >> 5, kk = C & 31;
        float bb0 = b1s[nl], bb1 = b1s[nl + 1];
        uint32_t hp, lp;
        float v0 = gelu(c[i][jt][0] + bb0);
        float v1 = gelu(c[i][jt][1] + bb1);
        split2(v0, v1, hp, lp);
        char* pp = g_h1img + gbase + (size_t)slot * 16384 + sw64((uint32_t)r0 * 64 + kk * 2);
        *(uint32_t*)pp = hp; *(uint32_t*)(pp + 8192) = lp;
        v0 = gelu(c[i][jt][2] + bb0);
        v1 = gelu(c[i][jt][3] + bb1);
        split2(v0, v1, hp, lp);
        pp = g_h1img + gbase + (size_t)slot * 16384 + sw64((uint32_t)(r0 + 8) * 64 + kk * 2);
        *(uint32_t*)pp = hp; *(uint32_t*)(pp + 8192) = lp;
    }
}

// ============ k2: partial = sum_n gelu(h1 @ W2 + b2) * W3 ============
// grid (4, 1000). 384 threads: 8 consumer + 4 producer warps. 16 K32 tiles, depth-3 ring.
__global__ void __launch_bounds__(384, 1)
k2(const float* __restrict__ W2, const float* __restrict__ b2, const float* __restrict__ W3)
{
    extern __shared__ char sm[];
    uint32_t sb = smem_u32(sm);
    const int nc = blockIdx.x, g = blockIdx.y;
    const int tid = threadIdx.x;
    const char* h1g = g_h1img + (size_t)g * 262144;

    if (tid >= 256){
        // ---------------- producer ----------------
        const int p = tid - 256;
        const float* Wg = W2 + (size_t)g * 262144 + nc * 128 + p;

        // cpA(kt) into ring slot: 16KB, 8 CP16/thread
        auto cpA = [&](int kt){
            const char* src = h1g + (size_t)kt * 16384;
            uint32_t dst = sb + K2_R + (kt % 3) * 32768;
#pragma unroll
            for (int i = 0; i < 8; i++){
                uint32_t idx = p + i * 128;
                CP16(dst + idx * 16, src + idx * 16);
            }
        };

        cpA(0); CPCOMMIT();
        float w0[32], w1[32];
#pragma unroll
        for (int l = 0; l < 32; l++) w0[l] = Wg[(size_t)l * 512];
#pragma unroll
        for (int l = 0; l < 32; l++) w1[l] = Wg[(size_t)(32 + l) * 512];

        for (int kt = 0; kt < 16; kt++){
            if (kt + 1 < 16){
                if (kt + 1 >= 3) BSYNC(BEMPTY + (kt + 1) % 3);
                cpA(kt + 1); CPCOMMIT();
            }
            // convert + STS B(kt)
            {
                float* wb = (kt & 1) ? w1 : w0;
                convSts(sm + K2_R + (kt % 3) * 32768 + 16384, p, wb);
                if (kt + 2 < 16){
#pragma unroll
                    for (int l = 0; l < 32; l++)
                        wb[l] = Wg[(size_t)((kt + 2) * 32 + l) * 512];
                }
            }
            if (kt + 1 < 16) CPWAIT1(); else CPWAIT0();
            BARR(BFULL + kt % 3);
        }
        return;
    }

    // ---------------- consumer ----------------
    const int lane = tid & 31, w = tid >> 5;
    const int wm = w & 1, wn = w >> 1;
    float* b2s = (float*)sm;
    float* w3s = (float*)(sm + 512);
    if (tid < 128){
        b2s[tid] = b2[(size_t)g * 512 + nc * 128 + tid];
        w3s[tid] = W3[(size_t)g * 512 + nc * 128 + tid];
    }

    float c[4][4][4];
#pragma unroll
    for (int i = 0; i < 4; i++)
#pragma unroll
    for (int jt = 0; jt < 4; jt++)
#pragma unroll
    for (int q = 0; q < 4; q++) c[i][jt][q] = 0.0f;
    Frag f = mk_frag(lane, wm, wn);

    for (int kt = 0; kt < 16; kt++){
        BSYNC(BFULL + kt % 3);
        uint32_t slot = sb + K2_R + (kt % 3) * 32768;
        mma32(slot, slot + 16384, f, c);
        if (kt <= 12) BARR(BEMPTY + kt % 3);   // only where a producer will wait
    }

    // epilogue: bias + gelu + W3-dot; quad shuffle + consumer-only smem reduce
    float* red = (float*)(sm + 1024);
#pragma unroll
    for (int i = 0; i < 4; i++){
        float s0 = 0.0f, s1 = 0.0f;
#pragma unroll
        for (int jt = 0; jt < 4; jt++){
            int nl = wn * 32 + jt * 8 + 2 * (lane & 3);
            float bb0 = b2s[nl], bb1 = b2s[nl+1], ww0 = w3s[nl], ww1 = w3s[nl+1];
            s0 += gelu(c[i][jt][0] + bb0) * ww0 + gelu(c[i][jt][1] + bb1) * ww1;
            s1 += gelu(c[i][jt][2] + bb0) * ww0 + gelu(c[i][jt][3] + bb1) * ww1;
        }
        s0 += __shfl_xor_sync(0xFFFFFFFFu, s0, 1);
        s0 += __shfl_xor_sync(0xFFFFFFFFu, s0, 2);
        s1 += __shfl_xor_sync(0xFFFFFFFFu, s1, 1);
        s1 += __shfl_xor_sync(0xFFFFFFFFu, s1, 2);
        if ((lane & 3) == 0){
            int r0 = wm * 64 + i * 16 + (lane >> 2);
            red[r0 * 4 + wn] = s0;
            red[(r0 + 8) * 4 + wn] = s1;
        }
    }
    BSYNCC();
    if (tid < 128){
        const float* rr = red + tid * 4;
        g_part[((size_t)g * 4 + nc) * 128 + tid] = (rr[0] + rr[1]) + (rr[2] + rr[3]);
    }
}

// ============ k3 ============
__global__ void k3(const float* __restrict__ b3, float* __restrict__ out)
{
    int idx = blockIdx.x * 256 + threadIdx.x;
    if (idx >= 128 * NG) return;
    int m = idx / NG;
    int g = idx - m * NG;
    const float* p = g_part + (size_t)g * 512 + m;
    out[idx] = b3[g] + ((p[0] + p[128]) + (p[256] + p[384]));
}

extern "C" void kernel_launch(void* const* d_in, const int* in_sizes, int n_in,
                              void* d_out, int out_size)
{
    const float* x  = (const float*)d_in[0];
    const float* W1 = (const float*)d_in[1];
    const float* b1 = (const float*)d_in[2];
    const float* W2 = (const float*)d_in[3];
    const float* b2 = (const float*)d_in[4];
    const float* W3 = (const float*)d_in[5];
    const float* b3 = (const float*)d_in[6];
    float* out = (float*)d_out;

    cudaFuncSetAttribute(k1, cudaFuncAttributeMaxDynamicSharedMemorySize, SM1_BYTES);
    cudaFuncSetAttribute(k2, cudaFuncAttributeMaxDynamicSharedMemorySize, SM2_BYTES);

    k0<<<1, 256>>>(x);
    dim3 grid(4, NG);
    k1<<<grid, 384, SM1_BYTES>>>(W1, b1);
    k2<<<grid, 384, SM2_BYTES>>>(W2, b2, W3);
    k3<<<(128 * NG + 255) / 256, 256>>>(b3, out);
}

// round 11
// speedup vs baseline: 1.2164x; 1.2164x over previous
#include <cuda_runtime.h>
#include <math.h>
#include <stdint.h>

#define NG 1000

// x as pre-swizzled bf16 hi/lo slot image: 4 slots x (hi 8K | lo 8K)
__device__ __align__(16) char g_ximg[65536];
// h1 as pre-swizzled slot image per gene: 16 slots x 16KB
__device__ __align__(16) char g_h1img[(size_t)NG * 262144];
__device__ float g_part[(size_t)NG * 4 * 128];

// k1 smem: b1s@0(1K) | A@1024 2x16K | B@33792 2x16K | WF@66560 2x16K = 99328
#define K1_A  1024
#define K1_B  33792
#define K1_WF 66560
#define SM1_BYTES 99328
// k2 smem: b2s@0 w3s@512 red@1024(3K) | A@4096 2x16K | B@36864 2x16K | WF@69632 2x16K = 102400
#define K2_A  4096
#define K2_B  36864
#define K2_WF 69632
#define SM2_BYTES 102400

__device__ __forceinline__ uint32_t smem_u32(const void* p){
    uint32_t a;
    asm("{ .reg .u64 t; cvta.to.shared.u64 t, %1; cvt.u32.u64 %0, t; }" : "=r"(a) : "l"(p));
    return a;
}
__device__ __forceinline__ uint32_t sw64(uint32_t x){ return x ^ ((x >> 3) & 0x30u); }

__device__ __forceinline__ void split2(float f0, float f1, uint32_t& hp, uint32_t& lp){
    asm("cvt.rn.bf16x2.f32 %0, %1, %2;" : "=r"(hp) : "f"(f1), "f"(f0));
    float h1f = __uint_as_float(hp & 0xFFFF0000u);
    float h0f = __uint_as_float(hp << 16);
    asm("cvt.rn.bf16x2.f32 %0, %1, %2;" : "=r"(lp) : "f"(f1 - h1f), "f"(f0 - h0f));
}
__device__ __forceinline__ float gelu(float v){
    return 0.5f * v * (1.0f + erff(v * 0.70710678118654752440f));
}
__device__ __forceinline__ void ldsm4(uint32_t* r, uint32_t a){
    asm volatile("ldmatrix.sync.aligned.m8n8.x4.shared.b16 {%0,%1,%2,%3}, [%4];"
      : "=r"(r[0]), "=r"(r[1]), "=r"(r[2]), "=r"(r[3]) : "r"(a));
}
__device__ __forceinline__ void mmabf(float* c, const uint32_t* a, uint32_t b0, uint32_t b1){
    asm volatile("mma.sync.aligned.m16n8k16.row.col.f32.bf16.bf16.f32 "
      "{%0,%1,%2,%3},{%4,%5,%6,%7},{%8,%9},{%0,%1,%2,%3};"
      : "+f"(c[0]), "+f"(c[1]), "+f"(c[2]), "+f"(c[3])
      : "r"(a[0]), "r"(a[1]), "r"(a[2]), "r"(a[3]), "r"(b0), "r"(b1));
}
#define CP16(d,s)  asm volatile("cp.async.cg.shared.global [%0], [%1], 16;" :: "r"(d), "l"(s) : "memory")
#define CPCOMMIT() asm volatile("cp.async.commit_group;" ::: "memory")
#define CPWAIT0()  asm volatile("cp.async.wait_group 0;" ::: "memory")

struct Frag { uint32_t offA, mA, offB, mB, ksel; };

__device__ __forceinline__ Frag mk_frag(int lane, int wm, int wn){
    Frag f;
    uint32_t rA = wm * 64 + (lane & 7) + ((lane >> 3) & 1) * 8;
    uint32_t rB = wn * 32 + (lane & 7) + ((lane >> 3) & 1) * 8;
    f.ksel = ((lane >> 4) & 1) * 16;
    f.mA = ((rA >> 1) & 3) << 4;  f.mB = ((rB >> 1) & 3) << 4;
    f.offA = rA * 64;             f.offB = rB * 64;
    return f;
}

// one K=32 tile, 64B rows. A: aB hi, aB+8192 lo; B: bB hi, bB+8192 lo.
__device__ __forceinline__ void mma32(uint32_t aB, uint32_t bB, const Frag& f, float c[4][4][4])
{
#pragma unroll
    for (int ks = 0; ks < 2; ks++){
        uint32_t ka = ks * 32 + f.ksel;
        uint32_t ao = f.offA + (ka ^ f.mA);
        uint32_t bo = f.offB + (ka ^ f.mB);
        uint32_t ah[4][4], al[4][4], bh[2][4], bl[2][4];
#pragma unroll
        for (int i = 0; i < 4; i++){ ldsm4(ah[i], aB + ao + i*1024u); ldsm4(al[i], aB + 8192u + ao + i*1024u); }
#pragma unroll
        for (int j = 0; j < 2; j++){ ldsm4(bh[j], bB + bo + j*1024u); ldsm4(bl[j], bB + 8192u + bo + j*1024u); }
#pragma unroll
        for (int i = 0; i < 4; i++)
#pragma unroll
        for (int jt = 0; jt < 4; jt++){
            int j = jt >> 1, s2 = jt & 1;
            mmabf(c[i][jt], ah[i], bh[j][s2], bh[j][s2+2]);
            mmabf(c[i][jt], ah[i], bl[j][s2], bl[j][s2+2]);
            mmabf(c[i][jt], al[i], bh[j][s2], bh[j][s2+2]);
        }
    }
}

// convert one W fp32 tile (smem [32k][128n], 512B rows) -> bf16 hi/lo planes
__device__ __forceinline__ void convW(const float* wf, char* bB, int nB, int khB){
    float fB[16];
#pragma unroll
    for (int l = 0; l < 16; l++) fB[l] = wf[(khB * 16 + l) * 128 + nB];
    char* Bh = bB; char* Bl = bB + 8192;
#pragma unroll
    for (int l = 0; l < 16; l += 4){
        uint32_t hp0, lp0, hp1, lp1;
        split2(fB[l],   fB[l+1], hp0, lp0);
        split2(fB[l+2], fB[l+3], hp1, lp1);
        uint32_t off = sw64((uint32_t)nB * 64 + khB * 32 + l * 2);
        *(uint2*)(Bh + off) = make_uint2(hp0, hp1);
        *(uint2*)(Bl + off) = make_uint2(lp0, lp1);
    }
}

// ============ k0: x -> pre-swizzled bf16 hi/lo image (once) ============
__global__ void k0(const float* __restrict__ x)
{
    int tid = threadIdx.x;           // 256
    int m = tid >> 1, h = tid & 1;
    const float4* xr = (const float4*)(x + m * 128 + h * 64);
#pragma unroll
    for (int j4 = 0; j4 < 16; j4++){
        float4 v = xr[j4];
        int l = j4 * 4;
        int slot = h * 2 + (l >> 5);
        int kk = l & 31;
        uint32_t hp0, lp0, hp1, lp1;
        split2(v.x, v.y, hp0, lp0);
        split2(v.z, v.w, hp1, lp1);
        uint32_t off = sw64((uint32_t)m * 64 + kk * 2);
        *(uint2*)(g_ximg + slot * 16384 + off) = make_uint2(hp0, hp1);
        *(uint2*)(g_ximg + slot * 16384 + 8192 + off) = make_uint2(lp0, lp1);
    }
}

// ============ k1: h1 = gelu(x @ W1 + b1) -> h1 slot image ============
// grid (4, 1000). 256 threads, 2 CTAs/SM. 4 K32 tiles, single-barrier windows.
__global__ void __launch_bounds__(256, 2)
k1(const float* __restrict__ W1, const float* __restrict__ b1)
{
    extern __shared__ char sm[];
    uint32_t sb = smem_u32(sm);
    const int nc = blockIdx.x, g = blockIdx.y;
    const int tid = threadIdx.x, lane = tid & 31, w = tid >> 5;
    const int wm = w & 1, wn = w >> 1;
    const int nB = tid & 127, khB = tid >> 7;

    const float* Wg = W1 + (size_t)g * 65536 + nc * 128;

    auto cpA = [&](int kt, int s){
        const char* src = g_ximg + (size_t)kt * 16384;
        uint32_t dst = sb + K1_A + s * 16384;
#pragma unroll
        for (int i = 0; i < 4; i++){
            uint32_t idx = tid + i * 256;
            CP16(dst + idx * 16, src + idx * 16);
        }
    };
    auto cpW = [&](int kt, int s){
        uint32_t dst = sb + K1_WF + s * 16384;
        const float* src = Wg + (size_t)kt * 32 * 512;
#pragma unroll
        for (int i = 0; i < 4; i++){
            uint32_t idx = tid + i * 256, k = idx >> 5, n4 = idx & 31;
            CP16(dst + k * 512 + n4 * 16, src + (size_t)k * 512 + n4 * 4);
        }
    };

    // prologue: A0, W0, W1 in one group
    cpA(0, 0); cpW(0, 0); cpW(1, 1); CPCOMMIT();
    float* b1s = (float*)sm;
    if (tid < 128) b1s[tid] = b1[(size_t)g * 512 + nc * 128 + tid];
    CPWAIT0();
    __syncthreads();
    convW((const float*)(sm + K1_WF), sm + K1_B, nB, khB);   // B0
    __syncthreads();

    float c[4][4][4];
#pragma unroll
    for (int i = 0; i < 4; i++)
#pragma unroll
    for (int jt = 0; jt < 4; jt++)
#pragma unroll
    for (int q = 0; q < 4; q++) c[i][jt][q] = 0.0f;
    Frag f = mk_frag(lane, wm, wn);

#pragma unroll
    for (int kt = 0; kt < 4; kt++){
        if (kt + 1 < 4){ cpA(kt + 1, (kt + 1) & 1); CPCOMMIT(); }
        if (kt + 2 < 4){ cpW(kt + 2, kt & 1); CPCOMMIT(); }
        if (kt + 1 < 4)
            convW((const float*)(sm + K1_WF + ((kt + 1) & 1) * 16384),
                  sm + K1_B + ((kt + 1) & 1) * 16384, nB, khB);
        mma32(sb + K1_A + (kt & 1) * 16384, sb + K1_B + (kt & 1) * 16384, f, c);
        CPWAIT0();
        __syncthreads();
    }

    // epilogue: bias + gelu + split -> smem image stage (64KB @ K1_A), then coalesced copy
    char* stage = sm + K1_A;
#pragma unroll
    for (int i = 0; i < 4; i++)
#pragma unroll
    for (int jt = 0; jt < 4; jt++){
        int nl = wn * 32 + jt * 8 + 2 * (lane & 3);
        int r0 = wm * 64 + i * 16 + (lane >> 2);
        int sl = nl >> 5, kk = nl & 31;
        float bb0 = b1s[nl], bb1 = b1s[nl + 1];
        uint32_t hp, lp;
        float v0 = gelu(c[i][jt][0] + bb0);
        float v1 = gelu(c[i][jt][1] + bb1);
        split2(v0, v1, hp, lp);
        char* pp = stage + sl * 16384 + sw64((uint32_t)r0 * 64 + kk * 2);
        *(uint32_t*)pp = hp; *(uint32_t*)(pp + 8192) = lp;
        v0 = gelu(c[i][jt][2] + bb0);
        v1 = gelu(c[i][jt][3] + bb1);
        split2(v0, v1, hp, lp);
        pp = stage + sl * 16384 + sw64((uint32_t)(r0 + 8) * 64 + kk * 2);
        *(uint32_t*)pp = hp; *(uint32_t*)(pp + 8192) = lp;
    }
    __syncthreads();
    {
        char* dst = g_h1img + (size_t)g * 262144 + (size_t)nc * 65536;
#pragma unroll
        for (int i = 0; i < 16; i++){
            uint32_t idx = tid + i * 256;
            *(uint4*)(dst + idx * 16) = *(uint4*)(stage + idx * 16);
        }
    }
}

// ============ k2: partial = sum_n gelu(h1 @ W2 + b2) * W3 ============
// grid (4, 1000). 256 threads, 2 CTAs/SM. 16 K32 tiles, single-barrier windows.
__global__ void __launch_bounds__(256, 2)
k2(const float* __restrict__ W2, const float* __restrict__ b2, const float* __restrict__ W3)
{
    extern __shared__ char sm[];
    uint32_t sb = smem_u32(sm);
    const int nc = blockIdx.x, g = blockIdx.y;
    const int tid = threadIdx.x, lane = tid & 31, w = tid >> 5;
    const int wm = w & 1, wn = w >> 1;
    const int nB = tid & 127, khB = tid >> 7;

    const char* h1g = g_h1img + (size_t)g * 262144;
    const float* Wg = W2 + (size_t)g * 262144 + nc * 128;

    auto cpA = [&](int kt, int s){
        const char* src = h1g + (size_t)kt * 16384;
        uint32_t dst = sb + K2_A + s * 16384;
#pragma unroll
        for (int i = 0; i < 4; i++){
            uint32_t idx = tid + i * 256;
            CP16(dst + idx * 16, src + idx * 16);
        }
    };
    auto cpW = [&](int kt, int s){
        uint32_t dst = sb + K2_WF + s * 16384;
        const float* src = Wg + (size_t)kt * 32 * 512;
#pragma unroll
        for (int i = 0; i < 4; i++){
            uint32_t idx = tid + i * 256, k = idx >> 5, n4 = idx & 31;
            CP16(dst + k * 512 + n4 * 16, src + (size_t)k * 512 + n4 * 4);
        }
    };

    // prologue
    cpA(0, 0); cpW(0, 0); cpW(1, 1); CPCOMMIT();
    float* b2s = (float*)sm;
    float* w3s = (float*)(sm + 512);
    if (tid < 128){
        b2s[tid] = b2[(size_t)g * 512 + nc * 128 + tid];
        w3s[tid] = W3[(size_t)g * 512 + nc * 128 + tid];
    }
    CPWAIT0();
    __syncthreads();
    convW((const float*)(sm + K2_WF), sm + K2_B, nB, khB);   // B0
    __syncthreads();

    float c[4][4][4];
#pragma unroll
    for (int i = 0; i < 4; i++)
#pragma unroll
    for (int jt = 0; jt < 4; jt++)
#pragma unroll
    for (int q = 0; q < 4; q++) c[i][jt][q] = 0.0f;
    Frag f = mk_frag(lane, wm, wn);

    for (int kt = 0; kt < 16; kt++){
        if (kt + 1 < 16){ cpA(kt + 1, (kt + 1) & 1); CPCOMMIT(); }
        if (kt + 2 < 16){ cpW(kt + 2, kt & 1); CPCOMMIT(); }
        if (kt + 1 < 16)
            convW((const float*)(sm + K2_WF + ((kt + 1) & 1) * 16384),
                  sm + K2_B + ((kt + 1) & 1) * 16384, nB, khB);
        mma32(sb + K2_A + (kt & 1) * 16384, sb + K2_B + (kt & 1) * 16384, f, c);
        CPWAIT0();
        __syncthreads();
    }

    // epilogue: bias + gelu + W3-dot; quad shuffle + smem reduce
    float* red = (float*)(sm + 1024);
#pragma unroll
    for (int i = 0; i < 4; i++){
        float s0 = 0.0f, s1 = 0.0f;
#pragma unroll
        for (int jt = 0; jt < 4; jt++){
            int nl = wn * 32 + jt * 8 + 2 * (lane & 3);
            float bb0 = b2s[nl], bb1 = b2s[nl+1], ww0 = w3s[nl], ww1 = w3s[nl+1];
            s0 += gelu(c[i][jt][0] + bb0) * ww0 + gelu(c[i][jt][1] + bb1) * ww1;
            s1 += gelu(c[i][jt][2] + bb0) * ww0 + gelu(c[i][jt][3] + bb1) * ww1;
        }
        s0 += __shfl_xor_sync(0xFFFFFFFFu, s0, 1);
        s0 += __shfl_xor_sync(0xFFFFFFFFu, s0, 2);
        s1 += __shfl_xor_sync(0xFFFFFFFFu, s1, 1);
        s1 += __shfl_xor_sync(0xFFFFFFFFu, s1, 2);
        if ((lane & 3) == 0){
            int r0 = wm * 64 + i * 16 + (lane >> 2);
            red[r0 * 4 + wn] = s0;
            red[(r0 + 8) * 4 + wn] = s1;
        }
    }
    __syncthreads();
    if (tid < 128){
        const float* rr = red + tid * 4;
        g_part[((size_t)g * 4 + nc) * 128 + tid] = (rr[0] + rr[1]) + (rr[2] + rr[3]);
    }
}

// ============ k3 ============
__global__ void k3(const float* __restrict__ b3, float* __restrict__ out)
{
    int idx = blockIdx.x * 256 + threadIdx.x;
    if (idx >= 128 * NG) return;
    int m = idx / NG;
    int g = idx - m * NG;
    const float* p = g_part + (size_t)g * 512 + m;
    out[idx] = b3[g] + ((p[0] + p[128]) + (p[256] + p[384]));
}

extern "C" void kernel_launch(void* const* d_in, const int* in_sizes, int n_in,
                              void* d_out, int out_size)
{
    const float* x  = (const float*)d_in[0];
    const float* W1 = (const float*)d_in[1];
    const float* b1 = (const float*)d_in[2];
    const float* W2 = (const float*)d_in[3];
    const float* b2 = (const float*)d_in[4];
    const float* W3 = (const float*)d_in[5];
    const float* b3 = (const float*)d_in[6];
    float* out = (float*)d_out;

    cudaFuncSetAttribute(k1, cudaFuncAttributeMaxDynamicSharedMemorySize, SM1_BYTES);
    cudaFuncSetAttribute(k2, cudaFuncAttributeMaxDynamicSharedMemorySize, SM2_BYTES);

    k0<<<1, 256>>>(x);
    dim3 grid(4, NG);
    k1<<<grid, 256, SM1_BYTES>>>(W1, b1);
    k2<<<grid, 256, SM2_BYTES>>>(W2, b2, W3);
    k3<<<(128 * NG + 255) / 256, 256>>>(b3, out);
}

// round 12
// speedup vs baseline: 1.2570x; 1.0334x over previous
#include <cuda_runtime.h>
#include <math.h>
#include <stdint.h>

#define NG 1000

// x as pre-swizzled bf16 hi/lo slot image: 4 slots x (hi 8K | lo 8K)
__device__ __align__(16) char g_ximg[65536];
// h1 as pre-swizzled slot image per gene: 16 slots x 16KB
__device__ __align__(16) char g_h1img[(size_t)NG * 262144];
__device__ float g_part[(size_t)NG * 4 * 128];

// k1 smem: b1s@0(1K) | A@1024 2x16K | B@33792 2x16K | WF@66560 2x16K = 99328
#define K1_A  1024
#define K1_B  33792
#define K1_WF 66560
#define SM1_BYTES 99328
// k2 smem: b2s@0 w3s@512 red@1024(3K) | A@4096 2x16K | B@36864 2x16K | WF@69632 2x16K = 102400
#define K2_A  4096
#define K2_B  36864
#define K2_WF 69632
#define SM2_BYTES 102400

__device__ __forceinline__ uint32_t smem_u32(const void* p){
    uint32_t a;
    asm("{ .reg .u64 t; cvta.to.shared.u64 t, %1; cvt.u32.u64 %0, t; }" : "=r"(a) : "l"(p));
    return a;
}
__device__ __forceinline__ uint32_t sw64(uint32_t x){ return x ^ ((x >> 3) & 0x30u); }

__device__ __forceinline__ void split2(float f0, float f1, uint32_t& hp, uint32_t& lp){
    asm("cvt.rn.bf16x2.f32 %0, %1, %2;" : "=r"(hp) : "f"(f1), "f"(f0));
    float h1f = __uint_as_float(hp & 0xFFFF0000u);
    float h0f = __uint_as_float(hp << 16);
    asm("cvt.rn.bf16x2.f32 %0, %1, %2;" : "=r"(lp) : "f"(f1 - h1f), "f"(f0 - h0f));
}
__device__ __forceinline__ float gelu(float v){
    return 0.5f * v * (1.0f + erff(v * 0.70710678118654752440f));
}
__device__ __forceinline__ void ldsm4(uint32_t* r, uint32_t a){
    asm volatile("ldmatrix.sync.aligned.m8n8.x4.shared.b16 {%0,%1,%2,%3}, [%4];"
      : "=r"(r[0]), "=r"(r[1]), "=r"(r[2]), "=r"(r[3]) : "r"(a));
}
__device__ __forceinline__ void mmabf(float* c, const uint32_t* a, uint32_t b0, uint32_t b1){
    asm volatile("mma.sync.aligned.m16n8k16.row.col.f32.bf16.bf16.f32 "
      "{%0,%1,%2,%3},{%4,%5,%6,%7},{%8,%9},{%0,%1,%2,%3};"
      : "+f"(c[0]), "+f"(c[1]), "+f"(c[2]), "+f"(c[3])
      : "r"(a[0]), "r"(a[1]), "r"(a[2]), "r"(a[3]), "r"(b0), "r"(b1));
}
#define CP16(d,s)  asm volatile("cp.async.cg.shared.global [%0], [%1], 16;" :: "r"(d), "l"(s) : "memory")
#define CPCOMMIT() asm volatile("cp.async.commit_group;" ::: "memory")
#define CPWAIT0()  asm volatile("cp.async.wait_group 0;" ::: "memory")

struct Frag { uint32_t offA, mA, offB, mB, ksel; };

__device__ __forceinline__ Frag mk_frag(int lane, int wm, int wn){
    Frag f;
    uint32_t rA = wm * 64 + (lane & 7) + ((lane >> 3) & 1) * 8;
    uint32_t rB = wn * 32 + (lane & 7) + ((lane >> 3) & 1) * 8;
    f.ksel = ((lane >> 4) & 1) * 16;
    f.mA = ((rA >> 1) & 3) << 4;  f.mB = ((rB >> 1) & 3) << 4;
    f.offA = rA * 64;             f.offB = rB * 64;
    return f;
}

// one K=32 tile, 64B rows. A: aB hi, aB+8192 lo; B: bB hi, bB+8192 lo.
// MMA issue order: split-term OUTERMOST so consecutive MMAs hit different
// accumulators (16 independent insts between same-acc revisits -> no RAW stall).
__device__ __forceinline__ void mma32(uint32_t aB, uint32_t bB, const Frag& f, float c[4][4][4])
{
#pragma unroll
    for (int ks = 0; ks < 2; ks++){
        uint32_t ka = ks * 32 + f.ksel;
        uint32_t ao = f.offA + (ka ^ f.mA);
        uint32_t bo = f.offB + (ka ^ f.mB);
        uint32_t ah[4][4], al[4][4], bh[2][4], bl[2][4];
#pragma unroll
        for (int i = 0; i < 4; i++){ ldsm4(ah[i], aB + ao + i*1024u); ldsm4(al[i], aB + 8192u + ao + i*1024u); }
#pragma unroll
        for (int j = 0; j < 2; j++){ ldsm4(bh[j], bB + bo + j*1024u); ldsm4(bl[j], bB + 8192u + bo + j*1024u); }
        // term 1: Ah*Bh
#pragma unroll
        for (int i = 0; i < 4; i++)
#pragma unroll
        for (int jt = 0; jt < 4; jt++){
            int j = jt >> 1, s2 = jt & 1;
            mmabf(c[i][jt], ah[i], bh[j][s2], bh[j][s2+2]);
        }
        // term 2: Ah*Bl
#pragma unroll
        for (int i = 0; i < 4; i++)
#pragma unroll
        for (int jt = 0; jt < 4; jt++){
            int j = jt >> 1, s2 = jt & 1;
            mmabf(c[i][jt], ah[i], bl[j][s2], bl[j][s2+2]);
        }
        // term 3: Al*Bh
#pragma unroll
        for (int i = 0; i < 4; i++)
#pragma unroll
        for (int jt = 0; jt < 4; jt++){
            int j = jt >> 1, s2 = jt & 1;
            mmabf(c[i][jt], al[i], bh[j][s2], bh[j][s2+2]);
        }
    }
}

// convert one W fp32 tile (smem [32k][128n], 512B rows) -> bf16 hi/lo planes
__device__ __forceinline__ void convW(const float* wf, char* bB, int nB, int khB){
    float fB[16];
#pragma unroll
    for (int l = 0; l < 16; l++) fB[l] = wf[(khB * 16 + l) * 128 + nB];
    char* Bh = bB; char* Bl = bB + 8192;
#pragma unroll
    for (int l = 0; l < 16; l += 4){
        uint32_t hp0, lp0, hp1, lp1;
        split2(fB[l],   fB[l+1], hp0, lp0);
        split2(fB[l+2], fB[l+3], hp1, lp1);
        uint32_t off = sw64((uint32_t)nB * 64 + khB * 32 + l * 2);
        *(uint2*)(Bh + off) = make_uint2(hp0, hp1);
        *(uint2*)(Bl + off) = make_uint2(lp0, lp1);
    }
}

// ============ k0: x -> pre-swizzled bf16 hi/lo image (once) ============
__global__ void k0(const float* __restrict__ x)
{
    int tid = threadIdx.x;           // 256
    int m = tid >> 1, h = tid & 1;
    const float4* xr = (const float4*)(x + m * 128 + h * 64);
#pragma unroll
    for (int j4 = 0; j4 < 16; j4++){
        float4 v = xr[j4];
        int l = j4 * 4;
        int slot = h * 2 + (l >> 5);
        int kk = l & 31;
        uint32_t hp0, lp0, hp1, lp1;
        split2(v.x, v.y, hp0, lp0);
        split2(v.z, v.w, hp1, lp1);
        uint32_t off = sw64((uint32_t)m * 64 + kk * 2);
        *(uint2*)(g_ximg + slot * 16384 + off) = make_uint2(hp0, hp1);
        *(uint2*)(g_ximg + slot * 16384 + 8192 + off) = make_uint2(lp0, lp1);
    }
}

// ============ k1: h1 = gelu(x @ W1 + b1) -> h1 slot image ============
// grid (4, 1000). 256 threads, 2 CTAs/SM. 4 K32 tiles, single-barrier windows.
__global__ void __launch_bounds__(256, 2)
k1(const float* __restrict__ W1, const float* __restrict__ b1)
{
    extern __shared__ char sm[];
    uint32_t sb = smem_u32(sm);
    const int nc = blockIdx.x, g = blockIdx.y;
    const int tid = threadIdx.x, lane = tid & 31, w = tid >> 5;
    const int wm = w & 1, wn = w >> 1;
    const int nB = tid & 127, khB = tid >> 7;

    const float* Wg = W1 + (size_t)g * 65536 + nc * 128;

    auto cpA = [&](int kt, int s){
        const char* src = g_ximg + (size_t)kt * 16384;
        uint32_t dst = sb + K1_A + s * 16384;
#pragma unroll
        for (int i = 0; i < 4; i++){
            uint32_t idx = tid + i * 256;
            CP16(dst + idx * 16, src + idx * 16);
        }
    };
    auto cpW = [&](int kt, int s){
        uint32_t dst = sb + K1_WF + s * 16384;
        const float* src = Wg + (size_t)kt * 32 * 512;
#pragma unroll
        for (int i = 0; i < 4; i++){
            uint32_t idx = tid + i * 256, k = idx >> 5, n4 = idx & 31;
            CP16(dst + k * 512 + n4 * 16, src + (size_t)k * 512 + n4 * 4);
        }
    };

    // prologue: A0, W0, W1 in one group
    cpA(0, 0); cpW(0, 0); cpW(1, 1); CPCOMMIT();
    float* b1s = (float*)sm;
    if (tid < 128) b1s[tid] = b1[(size_t)g * 512 + nc * 128 + tid];
    CPWAIT0();
    __syncthreads();
    convW((const float*)(sm + K1_WF), sm + K1_B, nB, khB);   // B0
    __syncthreads();

    float c[4][4][4];
#pragma unroll
    for (int i = 0; i < 4; i++)
#pragma unroll
    for (int jt = 0; jt < 4; jt++)
#pragma unroll
    for (int q = 0; q < 4; q++) c[i][jt][q] = 0.0f;
    Frag f = mk_frag(lane, wm, wn);

#pragma unroll
    for (int kt = 0; kt < 4; kt++){
        if (kt + 1 < 4){ cpA(kt + 1, (kt + 1) & 1); CPCOMMIT(); }
        if (kt + 2 < 4){ cpW(kt + 2, kt & 1); CPCOMMIT(); }
        if (kt + 1 < 4)
            convW((const float*)(sm + K1_WF + ((kt + 1) & 1) * 16384),
                  sm + K1_B + ((kt + 1) & 1) * 16384, nB, khB);
        mma32(sb + K1_A + (kt & 1) * 16384, sb + K1_B + (kt & 1) * 16384, f, c);
        CPWAIT0();
        __syncthreads();
    }

    // epilogue: bias + gelu + split -> smem image stage (64KB @ K1_A), then coalesced copy
    char* stage = sm + K1_A;
#pragma unroll
    for (int i = 0; i < 4; i++)
#pragma unroll
    for (int jt = 0; jt < 4; jt++){
        int nl = wn * 32 + jt * 8 + 2 * (lane & 3);
        int r0 = wm * 64 + i * 16 + (lane >> 2);
        int sl = nl >> 5, kk = nl & 31;
        float bb0 = b1s[nl], bb1 = b1s[nl + 1];
        uint32_t hp, lp;
        float v0 = gelu(c[i][jt][0] + bb0);
        float v1 = gelu(c[i][jt][1] + bb1);
        split2(v0, v1, hp, lp);
        char* pp = stage + sl * 16384 + sw64((uint32_t)r0 * 64 + kk * 2);
        *(uint32_t*)pp = hp; *(uint32_t*)(pp + 8192) = lp;
        v0 = gelu(c[i][jt][2] + bb0);
        v1 = gelu(c[i][jt][3] + bb1);
        split2(v0, v1, hp, lp);
        pp = stage + sl * 16384 + sw64((uint32_t)(r0 + 8) * 64 + kk * 2);
        *(uint32_t*)pp = hp; *(uint32_t*)(pp + 8192) = lp;
    }
    __syncthreads();
    {
        char* dst = g_h1img + (size_t)g * 262144 + (size_t)nc * 65536;
#pragma unroll
        for (int i = 0; i < 16; i++){
            uint32_t idx = tid + i * 256;
            *(uint4*)(dst + idx * 16) = *(uint4*)(stage + idx * 16);
        }
    }
}

// ============ k2: partial = sum_n gelu(h1 @ W2 + b2) * W3 ============
// grid (4, 1000). 256 threads, 2 CTAs/SM. 16 K32 tiles, single-barrier windows.
__global__ void __launch_bounds__(256, 2)
k2(const float* __restrict__ W2, const float* __restrict__ b2, const float* __restrict__ W3)
{
    extern __shared__ char sm[];
    uint32_t sb = smem_u32(sm);
    const int nc = blockIdx.x, g = blockIdx.y;
    const int tid = threadIdx.x, lane = tid & 31, w = tid >> 5;
    const int wm = w & 1, wn = w >> 1;
    const int nB = tid & 127, khB = tid >> 7;

    const char* h1g = g_h1img + (size_t)g * 262144;
    const float* Wg = W2 + (size_t)g * 262144 + nc * 128;

    auto cpA = [&](int kt, int s){
        const char* src = h1g + (size_t)kt * 16384;
        uint32_t dst = sb + K2_A + s * 16384;
#pragma unroll
        for (int i = 0; i < 4; i++){
            uint32_t idx = tid + i * 256;
            CP16(dst + idx * 16, src + idx * 16);
        }
    };
    auto cpW = [&](int kt, int s){
        uint32_t dst = sb + K2_WF + s * 16384;
        const float* src = Wg + (size_t)kt * 32 * 512;
#pragma unroll
        for (int i = 0; i < 4; i++){
            uint32_t idx = tid + i * 256, k = idx >> 5, n4 = idx & 31;
            CP16(dst + k * 512 + n4 * 16, src + (size_t)k * 512 + n4 * 4);
        }
    };

    // prologue
    cpA(0, 0); cpW(0, 0); cpW(1, 1); CPCOMMIT();
    float* b2s = (float*)sm;
    float* w3s = (float*)(sm + 512);
    if (tid < 128){
        b2s[tid] = b2[(size_t)g * 512 + nc * 128 + tid];
        w3s[tid] = W3[(size_t)g * 512 + nc * 128 + tid];
    }
    CPWAIT0();
    __syncthreads();
    convW((const float*)(sm + K2_WF), sm + K2_B, nB, khB);   // B0
    __syncthreads();

    float c[4][4][4];
#pragma unroll
    for (int i = 0; i < 4; i++)
#pragma unroll
    for (int jt = 0; jt < 4; jt++)
#pragma unroll
    for (int q = 0; q < 4; q++) c[i][jt][q] = 0.0f;
    Frag f = mk_frag(lane, wm, wn);

    for (int kt = 0; kt < 16; kt++){
        if (kt + 1 < 16){ cpA(kt + 1, (kt + 1) & 1); CPCOMMIT(); }
        if (kt + 2 < 16){ cpW(kt + 2, kt & 1); CPCOMMIT(); }
        if (kt + 1 < 16)
            convW((const float*)(sm + K2_WF + ((kt + 1) & 1) * 16384),
                  sm + K2_B + ((kt + 1) & 1) * 16384, nB, khB);
        mma32(sb + K2_A + (kt & 1) * 16384, sb + K2_B + (kt & 1) * 16384, f, c);
        CPWAIT0();
        __syncthreads();
    }

    // epilogue: bias + gelu + W3-dot; quad shuffle + smem reduce
    float* red = (float*)(sm + 1024);
#pragma unroll
    for (int i = 0; i < 4; i++){
        float s0 = 0.0f, s1 = 0.0f;
#pragma unroll
        for (int jt = 0; jt < 4; jt++){
            int nl = wn * 32 + jt * 8 + 2 * (lane & 3);
            float bb0 = b2s[nl], bb1 = b2s[nl+1], ww0 = w3s[nl], ww1 = w3s[nl+1];
            s0 += gelu(c[i][jt][0] + bb0) * ww0 + gelu(c[i][jt][1] + bb1) * ww1;
            s1 += gelu(c[i][jt][2] + bb0) * ww0 + gelu(c[i][jt][3] + bb1) * ww1;
        }
        s0 += __shfl_xor_sync(0xFFFFFFFFu, s0, 1);
        s0 += __shfl_xor_sync(0xFFFFFFFFu, s0, 2);
        s1 += __shfl_xor_sync(0xFFFFFFFFu, s1, 1);
        s1 += __shfl_xor_sync(0xFFFFFFFFu, s1, 2);
        if ((lane & 3) == 0){
            int r0 = wm * 64 + i * 16 + (lane >> 2);
            red[r0 * 4 + wn] = s0;
            red[(r0 + 8) * 4 + wn] = s1;
        }
    }
    __syncthreads();
    if (tid < 128){
        const float* rr = red + tid * 4;
        g_part[((size_t)g * 4 + nc) * 128 + tid] = (rr[0] + rr[1]) + (rr[2] + rr[3]);
    }
}

// ============ k3 ============
__global__ void k3(const float* __restrict__ b3, float* __restrict__ out)
{
    int idx = blockIdx.x * 256 + threadIdx.x;
    if (idx >= 128 * NG) return;
    int m = idx / NG;
    int g = idx - m * NG;
    const float* p = g_part + (size_t)g * 512 + m;
    out[idx] = b3[g] + ((p[0] + p[128]) + (p[256] + p[384]));
}

extern "C" void kernel_launch(void* const* d_in, const int* in_sizes, int n_in,
                              void* d_out, int out_size)
{
    const float* x  = (const float*)d_in[0];
    const float* W1 = (const float*)d_in[1];
    const float* b1 = (const float*)d_in[2];
    const float* W2 = (const float*)d_in[3];
    const float* b2 = (const float*)d_in[4];
    const float* W3 = (const float*)d_in[5];
    const float* b3 = (const float*)d_in[6];
    float* out = (float*)d_out;

    cudaFuncSetAttribute(k1, cudaFuncAttributeMaxDynamicSharedMemorySize, SM1_BYTES);
    cudaFuncSetAttribute(k2, cudaFuncAttributeMaxDynamicSharedMemorySize, SM2_BYTES);

    k0<<<1, 256>>>(x);
    dim3 grid(4, NG);
    k1<<<grid, 256, SM1_BYTES>>>(W1, b1);
    k2<<<grid, 256, SM2_BYTES>>>(W2, b2, W3);
    k3<<<(128 * NG + 255) / 256, 256>>>(b3, out);
}